// round 5
// baseline (speedup 1.0000x reference)
#include <cuda_runtime.h>

#define HH 256
#define WW 256
#define NW 8                // 256 cols / 32
#define NIMG 16             // 8 pred + 8 target
#define NPIX (8 * HH * WW)  // mean denominator

__device__ unsigned g_mask[NIMG][HH][NW];
__device__ unsigned g_flags[NIMG];  // bit0 = fgAny, bit1 = bgAny (monotone OR, idempotent)

// ---------------------------------------------------------------------------
// Kernel 1: build bitboard masks (1 bit per pixel), per-image flags, zero out.
// ---------------------------------------------------------------------------
__global__ void build_masks(const float* __restrict__ pred,
                            const float* __restrict__ target,
                            float* __restrict__ out) {
    int idx = blockIdx.x * blockDim.x + threadIdx.x;  // 0..32767
    if (idx == 0) *out = 0.0f;
    int img = idx >> 11;
    int rem = idx & 2047;
    int row = rem >> 3;
    int wj  = rem & 7;
    const float* src = (img < 8) ? (pred + (size_t)img * HH * WW)
                                 : (target + (size_t)(img - 8) * HH * WW);
    const float4* p4 = (const float4*)(src + row * WW + wj * 32);
    unsigned bits = 0;
#pragma unroll
    for (int k = 0; k < 8; ++k) {
        float4 v = p4[k];
        unsigned nib = (v.x > 0.5f ? 1u : 0u) | (v.y > 0.5f ? 2u : 0u) |
                       (v.z > 0.5f ? 4u : 0u) | (v.w > 0.5f ? 8u : 0u);
        bits |= nib << (4 * k);
    }
    g_mask[img][row][wj] = bits;
    unsigned fl = (bits ? 1u : 0u) | (bits != 0xFFFFFFFFu ? 2u : 0u);
#pragma unroll
    for (int o = 16; o > 0; o >>= 1) fl |= __shfl_xor_sync(0xFFFFFFFFu, fl, o);
    if ((threadIdx.x & 31) == 0) atomicOr(&g_flags[img], fl);
}

// ---------------------------------------------------------------------------
// Exact fallback: full scan for nearest opposite-class pixel (d2 >= 9 only;
// prob ~2^-24 per pixel on this data). 1e20 if no opposite pixel exists.
// ---------------------------------------------------------------------------
__device__ __noinline__ float slow_d2(int img, int i, int j, int c) {
    float best = 1e20f;
    for (int dd = 0; dd < HH; ++dd) {
        float dd2 = (float)(dd * dd);
        if (dd2 >= best) break;
#pragma unroll 1
        for (int s2 = 0; s2 < 2; ++s2) {
            if (s2 && dd == 0) continue;
            int r = s2 ? i - dd : i + dd;
            if (r < 0 || r >= HH) continue;
            for (int ww = 0; ww < NW; ++ww) {
                unsigned bm = g_mask[img][r][ww];
                if (c) bm = ~bm;
                while (bm) {
                    int p = __ffs(bm) - 1; bm &= bm - 1;
                    int dj = ww * 32 + p - j;
                    best = fminf(best, dd2 + (float)(dj * dj));
                }
            }
        }
    }
    return best;
}

// ---------------------------------------------------------------------------
// Kernel 2: two-phase fused loss. Block = (band of 8 rows, batch), 128 thr.
// Phase 1: thread = (image, row, word) task -> bit-planes p0..p3, true SIMD.
// Phase 2: warp = 2 rows, lane = pixel; s = p0+2p1+4p2+8p3 in {1,2,4,5,8};
//          acc += (p-t)^2 * (s_pred + s_target). s==0 -> deferred exact path.
// ---------------------------------------------------------------------------
__global__ void __launch_bounds__(128) loss_kernel(const float* __restrict__ pred,
                                                   const float* __restrict__ target,
                                                   float* __restrict__ out) {
    int band = blockIdx.x;          // 0..31
    int b    = blockIdx.y;          // 0..7
    int tid  = threadIdx.x;         // 0..127
    int lane = tid & 31;
    int wp   = tid >> 5;            // 0..3

    __shared__ unsigned SM[2][12][10];  // rows band*8-2..+9, zero-pad word cols 0,9
    __shared__ uint4    SP[2][8][NW];   // bit-planes per (img, row, word)
    __shared__ float    sred[4];

    unsigned flp = g_flags[b];
    unsigned flt = g_flags[b + 8];

    // stage masks + zero pads (disjoint writes, one barrier)
    if (tid < 48) {
        int f = tid / 24, rr = (tid >> 1) % 12, c = tid & 1;
        SM[f][rr][c * 9] = 0u;
    }
    for (int e = tid; e < 192; e += 128) {
        int f = e / 96, rr = (e >> 3) % 12, ww = e & 7;
        int gi = band * 8 - 2 + rr;
        gi = gi < 0 ? 0 : (gi > 255 ? 255 : gi);
        SM[f][rr][ww + 1] = g_mask[f ? b + 8 : b][gi][ww];
    }
    __syncthreads();

    // ---------------- Phase 1: one word-task per thread ----------------
    {
        int f1 = tid >> 6;          // 0 = pred, 1 = target
        int rr = (tid >> 3) & 7;    // row in band
        int w1 = tid & 7;           // word
        unsigned fl1 = f1 ? flt : flp;
        uint4 planes = make_uint4(0u, 0u, 0u, 0u);
        if (fl1 == 3u) {
            int i1 = band * 8 + rr;
            int sr = rr + 2;
            const unsigned (*M)[10] = SM[f1];
            unsigned W  = M[sr][w1 + 1];
            unsigned l0 = M[sr][w1],     r0 = M[sr][w1 + 2];
            unsigned cU = M[sr - 1][w1 + 1], lU = M[sr - 1][w1], rU = M[sr - 1][w1 + 2];
            unsigned cD = M[sr + 1][w1 + 1], lD = M[sr + 1][w1], rD = M[sr + 1][w1 + 2];
            unsigned mlo1 = (w1 == 0) ? 0xFFFFFFFEu : 0xFFFFFFFFu;
            unsigned mlo2 = (w1 == 0) ? 0xFFFFFFFCu : 0xFFFFFFFFu;
            unsigned mhi1 = (w1 == 7) ? 0x7FFFFFFFu : 0xFFFFFFFFu;
            unsigned mhi2 = (w1 == 7) ? 0x3FFFFFFFu : 0xFFFFFFFFu;
            unsigned rvU1 = (i1 >= 1)   ? 0xFFFFFFFFu : 0u;
            unsigned rvD1 = (i1 <= 254) ? 0xFFFFFFFFu : 0u;
            unsigned rvU2 = (i1 >= 2)   ? 0xFFFFFFFFu : 0u;
            unsigned rvD2 = (i1 <= 253) ? 0xFFFFFFFFu : 0u;

            // s=1: (0,+-1), (+-1,0)
            unsigned h1 = ((W ^ __funnelshift_l(l0, W, 1)) & mlo1)
                        | ((W ^ __funnelshift_r(W, r0, 1)) & mhi1)
                        | ((W ^ cU) & rvU1)
                        | ((W ^ cD) & rvD1);
            // s=2: (+-1,+-1)
            unsigned h2 = (((((W ^ __funnelshift_l(lU, cU, 1)) & mlo1)
                           | ((W ^ __funnelshift_r(cU, rU, 1)) & mhi1)) & rvU1)
                         | ((((W ^ __funnelshift_l(lD, cD, 1)) & mlo1)
                           | ((W ^ __funnelshift_r(cD, rD, 1)) & mhi1)) & rvD1)) & ~h1;
            unsigned p0 = h1, p1 = h2, p2 = 0u, p3 = 0u;
            unsigned U = ~(h1 | h2);
            if (U) {
                unsigned cUU = M[sr - 2][w1 + 1], lUU = M[sr - 2][w1], rUU = M[sr - 2][w1 + 2];
                unsigned cDD = M[sr + 2][w1 + 1], lDD = M[sr + 2][w1], rDD = M[sr + 2][w1 + 2];
                // s=4: (0,+-2), (+-2,0)
                unsigned h4 = (((W ^ __funnelshift_l(l0, W, 2)) & mlo2)
                             | ((W ^ __funnelshift_r(W, r0, 2)) & mhi2)
                             | ((W ^ cUU) & rvU2)
                             | ((W ^ cDD) & rvD2)) & U;
                p2 = h4;
                U &= ~h4;
                // s=5: (+-1,+-2), (+-2,+-1)
                unsigned h5 = (((((W ^ __funnelshift_l(lU, cU, 2)) & mlo2)
                               | ((W ^ __funnelshift_r(cU, rU, 2)) & mhi2)) & rvU1)
                             | ((((W ^ __funnelshift_l(lD, cD, 2)) & mlo2)
                               | ((W ^ __funnelshift_r(cD, rD, 2)) & mhi2)) & rvD1)
                             | ((((W ^ __funnelshift_l(lUU, cUU, 1)) & mlo1)
                               | ((W ^ __funnelshift_r(cUU, rUU, 1)) & mhi1)) & rvU2)
                             | ((((W ^ __funnelshift_l(lDD, cDD, 1)) & mlo1)
                               | ((W ^ __funnelshift_r(cDD, rDD, 1)) & mhi1)) & rvD2)) & U;
                p0 |= h5;
                p2 |= h5;
                U &= ~h5;
                // s=8: (+-2,+-2)
                unsigned h8 = (((((W ^ __funnelshift_l(lUU, cUU, 2)) & mlo2)
                               | ((W ^ __funnelshift_r(cUU, rUU, 2)) & mhi2)) & rvU2)
                             | ((((W ^ __funnelshift_l(lDD, cDD, 2)) & mlo2)
                               | ((W ^ __funnelshift_r(cDD, rDD, 2)) & mhi2)) & rvD2)) & U;
                p3 = h8;
                // any pixel still unresolved keeps all-planes-0 -> s==0 marker
            }
            planes = make_uint4(p0, p1, p2, p3);
        }
        SP[f1][rr][w1] = planes;
    }
    __syncthreads();

    // ---------------- Phase 2: warp = 2 rows, lane = pixel ----------------
    float acc = 0.0f;
    unsigned fb = 0u;  // deferred fallback events: bit = ((rsub*8+ww)<<1)|side

    bool both3 = (flp == 3u) && (flt == 3u);
#pragma unroll
    for (int rsub = 0; rsub < 2; ++rsub) {
        int r  = wp * 2 + rsub;
        int i2 = band * 8 + r;
        const float* prow = pred   + ((size_t)b * HH + i2) * WW;
        const float* trow = target + ((size_t)b * HH + i2) * WW;
#pragma unroll
        for (int ww = 0; ww < NW; ++ww) {
            float d = prow[ww * 32 + lane] - trow[ww * 32 + lane];
            float w = d * d;
            int k2 = ((rsub * 8 + ww) << 1);
            if (both3) {  // common case: single I2F for combined scale
                uint4 P = SP[0][r][ww];
                uint4 Q = SP[1][r][ww];
                int sp = (int)((P.x >> lane) & 1u) | ((int)((P.y >> lane) & 1u) << 1)
                       | ((int)((P.z >> lane) & 1u) << 2) | ((int)((P.w >> lane) & 1u) << 3);
                int st = (int)((Q.x >> lane) & 1u) | ((int)((Q.y >> lane) & 1u) << 1)
                       | ((int)((Q.z >> lane) & 1u) << 2) | ((int)((Q.w >> lane) & 1u) << 3);
                fb |= (sp == 0 ? 1u : 0u) << k2;
                fb |= (st == 0 ? 2u : 0u) << k2;
                acc += w * (float)(sp + st);
            } else {
                float ssum = 0.0f;
                if (flp == 3u) {
                    uint4 P = SP[0][r][ww];
                    int sp = (int)((P.x >> lane) & 1u) | ((int)((P.y >> lane) & 1u) << 1)
                           | ((int)((P.z >> lane) & 1u) << 2) | ((int)((P.w >> lane) & 1u) << 3);
                    fb |= (sp == 0 ? 1u : 0u) << k2;
                    ssum += (float)sp;
                } else if (flp & 1u) ssum += 1e20f;  // all-fg: d2 = (1e10)^2
                if (flt == 3u) {
                    uint4 Q = SP[1][r][ww];
                    int st = (int)((Q.x >> lane) & 1u) | ((int)((Q.y >> lane) & 1u) << 1)
                           | ((int)((Q.z >> lane) & 1u) << 2) | ((int)((Q.w >> lane) & 1u) << 3);
                    fb |= (st == 0 ? 2u : 0u) << k2;
                    ssum += (float)st;
                } else if (flt & 1u) ssum += 1e20f;
                acc += w * ssum;
            }
        }
    }

    // deferred exact fallback (d2 >= 9; astronomically rare on this data)
    if (fb) {
        while (fb) {
            int e = __ffs(fb) - 1; fb &= fb - 1;
            int side = e & 1;
            int k = e >> 1;
            int rsub = k >> 3, ww = k & 7;
            int r  = wp * 2 + rsub;
            int i2 = band * 8 + r;
            int col = ww * 32 + lane;
            float d = pred[((size_t)b * HH + i2) * WW + col]
                    - target[((size_t)b * HH + i2) * WW + col];
            int img = side ? b + 8 : b;
            int c = (int)((SM[side][r + 2][ww + 1] >> lane) & 1u);
            acc += d * d * slow_d2(img, i2, col, c);
        }
    }

    // reduce: warp -> block -> global
#pragma unroll
    for (int o = 16; o > 0; o >>= 1) acc += __shfl_xor_sync(0xFFFFFFFFu, acc, o);
    if (lane == 0) sred[wp] = acc;
    __syncthreads();
    if (tid == 0) {
        float sum = sred[0] + sred[1] + sred[2] + sred[3];
        atomicAdd(out, sum * (1.0f / (float)NPIX));
    }
}

extern "C" void kernel_launch(void* const* d_in, const int* in_sizes, int n_in,
                              void* d_out, int out_size) {
    const float* pred   = (const float*)d_in[0];
    const float* target = (const float*)d_in[1];
    float* out = (float*)d_out;

    build_masks<<<128, 256>>>(pred, target, out);
    loss_kernel<<<dim3(32, 8), 128>>>(pred, target, out);
}

// round 6
// speedup vs baseline: 2.1253x; 2.1253x over previous
#include <cuda_runtime.h>

#define HH 256
#define WW 256
#define NW 8                // 256 cols / 32
#define NIMG 16             // 8 pred + 8 target
#define NPIX (8 * HH * WW)  // mean denominator

__device__ unsigned g_mask[NIMG][HH][NW];
__device__ unsigned g_flags[NIMG];  // bit0 = fgAny, bit1 = bgAny (monotone OR, idempotent)

// ---------------------------------------------------------------------------
// Kernel 1: build bitboard masks (1 bit per pixel), per-image flags, zero out.
// ---------------------------------------------------------------------------
__global__ void build_masks(const float* __restrict__ pred,
                            const float* __restrict__ target,
                            float* __restrict__ out) {
    int idx = blockIdx.x * blockDim.x + threadIdx.x;  // 0..32767
    if (idx == 0) *out = 0.0f;
    int img = idx >> 11;
    int rem = idx & 2047;
    int row = rem >> 3;
    int wj  = rem & 7;
    const float* src = (img < 8) ? (pred + (size_t)img * HH * WW)
                                 : (target + (size_t)(img - 8) * HH * WW);
    const float4* p4 = (const float4*)(src + row * WW + wj * 32);
    unsigned bits = 0;
#pragma unroll
    for (int k = 0; k < 8; ++k) {
        float4 v = p4[k];
        unsigned nib = (v.x > 0.5f ? 1u : 0u) | (v.y > 0.5f ? 2u : 0u) |
                       (v.z > 0.5f ? 4u : 0u) | (v.w > 0.5f ? 8u : 0u);
        bits |= nib << (4 * k);
    }
    g_mask[img][row][wj] = bits;
    unsigned fl = (bits ? 1u : 0u) | (bits != 0xFFFFFFFFu ? 2u : 0u);
#pragma unroll
    for (int o = 16; o > 0; o >>= 1) fl |= __shfl_xor_sync(0xFFFFFFFFu, fl, o);
    if ((threadIdx.x & 31) == 0) atomicOr(&g_flags[img], fl);
}

// ---------------------------------------------------------------------------
// Fast exact fallback (d2 >= 14 only; <1% probability of ANY event in this
// input). Word-level nearest-set-bit per row via ffs/clz: ~40 instr/row.
// Returns 1e20 if no opposite pixel exists anywhere.
// ---------------------------------------------------------------------------
__device__ __noinline__ float fast_d2(int img, int i, int j, int c) {
    float best = 1e20f;
    int jw = j >> 5, jb = j & 31;
    for (int dd = 0; dd < HH; ++dd) {
        float dd2 = (float)(dd * dd);
        if (dd2 >= best) break;
#pragma unroll 1
        for (int s2 = 0; s2 < 2; ++s2) {
            if (s2 && dd == 0) continue;
            int r = s2 ? i - dd : i + dd;
            if (r < 0 || r >= HH) continue;
            const unsigned* m = g_mask[img][r];
            int up = 1 << 20, dn = 1 << 20;
            unsigned own = c ? ~m[jw] : m[jw];
            // upward: cols >= j
            unsigned o = own & (0xFFFFFFFFu << jb);
            if (o) up = (__ffs(o) - 1) - jb;
            else {
                for (int w = jw + 1; w < NW; ++w) {
                    unsigned ow = c ? ~m[w] : m[w];
                    if (ow) { up = w * 32 + __ffs(ow) - 1 - j; break; }
                }
            }
            // downward: cols <= j
            unsigned o2 = own & (0xFFFFFFFFu >> (31 - jb));
            if (o2) dn = jb - (31 - __clz(o2));
            else {
                for (int w = jw - 1; w >= 0; --w) {
                    unsigned ow = c ? ~m[w] : m[w];
                    if (ow) { dn = j - (w * 32 + 31 - __clz(ow)); break; }
                }
            }
            int dj = up < dn ? up : dn;
            if (dj < (1 << 20))
                best = fminf(best, dd2 + (float)dj * (float)dj);
        }
    }
    return best;
}

// ---------------------------------------------------------------------------
// Kernel 2: two-phase fused loss. Block = (band of 8 rows, batch), 128 thr.
// Phase 1: thread = (image, row, word) -> bit-planes, levels r^2 in
//          {1,2,4,5,8} + gated {9,10,13}. s = p0+2p1+4p2+8p3.
// Phase 2: warp = 2 rows, lane = pixel; acc += (p-t)^2 * (s_pred+s_target).
// ---------------------------------------------------------------------------
__global__ void __launch_bounds__(128) loss_kernel(const float* __restrict__ pred,
                                                   const float* __restrict__ target,
                                                   float* __restrict__ out) {
    int band = blockIdx.x;          // 0..31
    int b    = blockIdx.y;          // 0..7
    int tid  = threadIdx.x;         // 0..127
    int lane = tid & 31;
    int wp   = tid >> 5;            // 0..3

    __shared__ unsigned SM[2][14][10];  // rows band*8-3..+10, zero-pad cols 0,9
    __shared__ uint4    SP[2][8][NW];
    __shared__ float    sred[4];

    unsigned flp = g_flags[b];
    unsigned flt = g_flags[b + 8];

    // stage masks + zero pads
    if (tid < 56) {
        int f = tid / 28, rr = (tid >> 1) % 14, cc = tid & 1;
        SM[f][rr][cc * 9] = 0u;
    }
    for (int e = tid; e < 224; e += 128) {
        int f = e / 112, rr = (e >> 3) % 14, ww = e & 7;
        int gi = band * 8 - 3 + rr;
        gi = gi < 0 ? 0 : (gi > 255 ? 255 : gi);
        SM[f][rr][ww + 1] = g_mask[f ? b + 8 : b][gi][ww];
    }
    __syncthreads();

    // ---------------- Phase 1: one word-task per thread ----------------
    {
        int f1 = tid >> 6;          // 0 = pred, 1 = target
        int rr = (tid >> 3) & 7;    // row in band
        int w1 = tid & 7;           // word
        unsigned fl1 = f1 ? flt : flp;
        uint4 planes = make_uint4(0u, 0u, 0u, 0u);
        if (fl1 == 3u) {
            int i1 = band * 8 + rr;
            int sr = rr + 3;
            const unsigned (*M)[10] = SM[f1];
            unsigned W  = M[sr][w1 + 1];
            unsigned l0 = M[sr][w1],         r0 = M[sr][w1 + 2];
            unsigned cU = M[sr - 1][w1 + 1], lU = M[sr - 1][w1], rU = M[sr - 1][w1 + 2];
            unsigned cD = M[sr + 1][w1 + 1], lD = M[sr + 1][w1], rD = M[sr + 1][w1 + 2];
            unsigned mlo1 = (w1 == 0) ? 0xFFFFFFFEu : 0xFFFFFFFFu;
            unsigned mlo2 = (w1 == 0) ? 0xFFFFFFFCu : 0xFFFFFFFFu;
            unsigned mlo3 = (w1 == 0) ? 0xFFFFFFF8u : 0xFFFFFFFFu;
            unsigned mhi1 = (w1 == 7) ? 0x7FFFFFFFu : 0xFFFFFFFFu;
            unsigned mhi2 = (w1 == 7) ? 0x3FFFFFFFu : 0xFFFFFFFFu;
            unsigned mhi3 = (w1 == 7) ? 0x1FFFFFFFu : 0xFFFFFFFFu;
            unsigned rvU1 = (i1 >= 1)   ? 0xFFFFFFFFu : 0u;
            unsigned rvD1 = (i1 <= 254) ? 0xFFFFFFFFu : 0u;
            unsigned rvU2 = (i1 >= 2)   ? 0xFFFFFFFFu : 0u;
            unsigned rvD2 = (i1 <= 253) ? 0xFFFFFFFFu : 0u;
            unsigned rvU3 = (i1 >= 3)   ? 0xFFFFFFFFu : 0u;
            unsigned rvD3 = (i1 <= 252) ? 0xFFFFFFFFu : 0u;

            // s=1: (0,+-1), (+-1,0)
            unsigned h1 = ((W ^ __funnelshift_l(l0, W, 1)) & mlo1)
                        | ((W ^ __funnelshift_r(W, r0, 1)) & mhi1)
                        | ((W ^ cU) & rvU1)
                        | ((W ^ cD) & rvD1);
            // s=2: (+-1,+-1)
            unsigned h2 = (((((W ^ __funnelshift_l(lU, cU, 1)) & mlo1)
                           | ((W ^ __funnelshift_r(cU, rU, 1)) & mhi1)) & rvU1)
                         | ((((W ^ __funnelshift_l(lD, cD, 1)) & mlo1)
                           | ((W ^ __funnelshift_r(cD, rD, 1)) & mhi1)) & rvD1)) & ~h1;
            unsigned p0 = h1, p1 = h2, p2 = 0u, p3 = 0u;
            unsigned U = ~(h1 | h2);
            if (U) {
                unsigned cUU = M[sr - 2][w1 + 1], lUU = M[sr - 2][w1], rUU = M[sr - 2][w1 + 2];
                unsigned cDD = M[sr + 2][w1 + 1], lDD = M[sr + 2][w1], rDD = M[sr + 2][w1 + 2];
                // s=4: (0,+-2), (+-2,0)
                unsigned h4 = (((W ^ __funnelshift_l(l0, W, 2)) & mlo2)
                             | ((W ^ __funnelshift_r(W, r0, 2)) & mhi2)
                             | ((W ^ cUU) & rvU2)
                             | ((W ^ cDD) & rvD2)) & U;
                p2 = h4;
                U &= ~h4;
                // s=5: (+-1,+-2), (+-2,+-1)
                unsigned h5 = (((((W ^ __funnelshift_l(lU, cU, 2)) & mlo2)
                               | ((W ^ __funnelshift_r(cU, rU, 2)) & mhi2)) & rvU1)
                             | ((((W ^ __funnelshift_l(lD, cD, 2)) & mlo2)
                               | ((W ^ __funnelshift_r(cD, rD, 2)) & mhi2)) & rvD1)
                             | ((((W ^ __funnelshift_l(lUU, cUU, 1)) & mlo1)
                               | ((W ^ __funnelshift_r(cUU, rUU, 1)) & mhi1)) & rvU2)
                             | ((((W ^ __funnelshift_l(lDD, cDD, 1)) & mlo1)
                               | ((W ^ __funnelshift_r(cDD, rDD, 1)) & mhi1)) & rvD2)) & U;
                p0 |= h5;
                p2 |= h5;
                U &= ~h5;
                // s=8: (+-2,+-2)
                unsigned h8 = (((((W ^ __funnelshift_l(lUU, cUU, 2)) & mlo2)
                               | ((W ^ __funnelshift_r(cUU, rUU, 2)) & mhi2)) & rvU2)
                             | ((((W ^ __funnelshift_l(lDD, cDD, 2)) & mlo2)
                               | ((W ^ __funnelshift_r(cDD, rDD, 2)) & mhi2)) & rvD2)) & U;
                p3 = h8;
                U &= ~h8;
                if (U) {  // essentially only border words ever get here
                    unsigned cU3 = M[sr - 3][w1 + 1], lU3 = M[sr - 3][w1], rU3 = M[sr - 3][w1 + 2];
                    unsigned cD3 = M[sr + 3][w1 + 1], lD3 = M[sr + 3][w1], rD3 = M[sr + 3][w1 + 2];
                    // s=9: (0,+-3), (+-3,0)
                    unsigned h9 = (((W ^ __funnelshift_l(l0, W, 3)) & mlo3)
                                 | ((W ^ __funnelshift_r(W, r0, 3)) & mhi3)
                                 | ((W ^ cU3) & rvU3)
                                 | ((W ^ cD3) & rvD3)) & U;
                    p0 |= h9; p3 |= h9;
                    U &= ~h9;
                    // s=10: (+-1,+-3), (+-3,+-1)
                    unsigned h10 = (((((W ^ __funnelshift_l(lU, cU, 3)) & mlo3)
                                    | ((W ^ __funnelshift_r(cU, rU, 3)) & mhi3)) & rvU1)
                                  | ((((W ^ __funnelshift_l(lD, cD, 3)) & mlo3)
                                    | ((W ^ __funnelshift_r(cD, rD, 3)) & mhi3)) & rvD1)
                                  | ((((W ^ __funnelshift_l(lU3, cU3, 1)) & mlo1)
                                    | ((W ^ __funnelshift_r(cU3, rU3, 1)) & mhi1)) & rvU3)
                                  | ((((W ^ __funnelshift_l(lD3, cD3, 1)) & mlo1)
                                    | ((W ^ __funnelshift_r(cD3, rD3, 1)) & mhi1)) & rvD3)) & U;
                    p1 |= h10; p3 |= h10;
                    U &= ~h10;
                    // s=13: (+-2,+-3), (+-3,+-2)
                    unsigned h13 = (((((W ^ __funnelshift_l(lUU, cUU, 3)) & mlo3)
                                    | ((W ^ __funnelshift_r(cUU, rUU, 3)) & mhi3)) & rvU2)
                                  | ((((W ^ __funnelshift_l(lDD, cDD, 3)) & mlo3)
                                    | ((W ^ __funnelshift_r(cDD, rDD, 3)) & mhi3)) & rvD2)
                                  | ((((W ^ __funnelshift_l(lU3, cU3, 2)) & mlo2)
                                    | ((W ^ __funnelshift_r(cU3, rU3, 2)) & mhi2)) & rvU3)
                                  | ((((W ^ __funnelshift_l(lD3, cD3, 2)) & mlo2)
                                    | ((W ^ __funnelshift_r(cD3, rD3, 2)) & mhi2)) & rvD3)) & U;
                    p0 |= h13; p2 |= h13; p3 |= h13;
                    // pixels still unresolved keep all-planes-0 -> fallback
                }
            }
            planes = make_uint4(p0, p1, p2, p3);
        }
        SP[f1][rr][w1] = planes;
    }
    __syncthreads();

    // ---------------- Phase 2: warp = 2 rows, lane = pixel ----------------
    float acc = 0.0f;
    unsigned fb = 0u;  // deferred fallback events: bit = ((rsub*8+ww)<<1)|side

    bool both3 = (flp == 3u) && (flt == 3u);
#pragma unroll
    for (int rsub = 0; rsub < 2; ++rsub) {
        int r  = wp * 2 + rsub;
        int i2 = band * 8 + r;
        const float* prow = pred   + ((size_t)b * HH + i2) * WW;
        const float* trow = target + ((size_t)b * HH + i2) * WW;
#pragma unroll
        for (int ww = 0; ww < NW; ++ww) {
            float d = prow[ww * 32 + lane] - trow[ww * 32 + lane];
            float w = d * d;
            int k2 = ((rsub * 8 + ww) << 1);
            if (both3) {
                uint4 P = SP[0][r][ww];
                uint4 Q = SP[1][r][ww];
                int sp = (int)((P.x >> lane) & 1u) | ((int)((P.y >> lane) & 1u) << 1)
                       | ((int)((P.z >> lane) & 1u) << 2) | ((int)((P.w >> lane) & 1u) << 3);
                int st = (int)((Q.x >> lane) & 1u) | ((int)((Q.y >> lane) & 1u) << 1)
                       | ((int)((Q.z >> lane) & 1u) << 2) | ((int)((Q.w >> lane) & 1u) << 3);
                fb |= (sp == 0 ? 1u : 0u) << k2;
                fb |= (st == 0 ? 2u : 0u) << k2;
                acc += w * (float)(sp + st);
            } else {
                float ssum = 0.0f;
                if (flp == 3u) {
                    uint4 P = SP[0][r][ww];
                    int sp = (int)((P.x >> lane) & 1u) | ((int)((P.y >> lane) & 1u) << 1)
                           | ((int)((P.z >> lane) & 1u) << 2) | ((int)((P.w >> lane) & 1u) << 3);
                    fb |= (sp == 0 ? 1u : 0u) << k2;
                    ssum += (float)sp;
                } else if (flp & 1u) ssum += 1e20f;  // all-fg: d2 = (1e10)^2
                if (flt == 3u) {
                    uint4 Q = SP[1][r][ww];
                    int st = (int)((Q.x >> lane) & 1u) | ((int)((Q.y >> lane) & 1u) << 1)
                           | ((int)((Q.z >> lane) & 1u) << 2) | ((int)((Q.w >> lane) & 1u) << 3);
                    fb |= (st == 0 ? 2u : 0u) << k2;
                    ssum += (float)st;
                } else if (flt & 1u) ssum += 1e20f;
                acc += w * ssum;
            }
        }
    }

    // deferred exact fallback (d2 >= 14; ~0.5% chance of ANY event, fast path)
    if (fb) {
        while (fb) {
            int e = __ffs(fb) - 1; fb &= fb - 1;
            int side = e & 1;
            int k = e >> 1;
            int rsub = k >> 3, ww = k & 7;
            int r  = wp * 2 + rsub;
            int i2 = band * 8 + r;
            int col = ww * 32 + lane;
            float d = pred[((size_t)b * HH + i2) * WW + col]
                    - target[((size_t)b * HH + i2) * WW + col];
            int img = side ? b + 8 : b;
            int c = (int)((SM[side][r + 3][ww + 1] >> lane) & 1u);
            acc += d * d * fast_d2(img, i2, col, c);
        }
    }

    // reduce: warp -> block -> global
#pragma unroll
    for (int o = 16; o > 0; o >>= 1) acc += __shfl_xor_sync(0xFFFFFFFFu, acc, o);
    if (lane == 0) sred[wp] = acc;
    __syncthreads();
    if (tid == 0) {
        float sum = sred[0] + sred[1] + sred[2] + sred[3];
        atomicAdd(out, sum * (1.0f / (float)NPIX));
    }
}

extern "C" void kernel_launch(void* const* d_in, const int* in_sizes, int n_in,
                              void* d_out, int out_size) {
    const float* pred   = (const float*)d_in[0];
    const float* target = (const float*)d_in[1];
    float* out = (float*)d_out;

    build_masks<<<128, 256>>>(pred, target, out);
    loss_kernel<<<dim3(32, 8), 128>>>(pred, target, out);
}